// round 15
// baseline (speedup 1.0000x reference)
#include <cuda_runtime.h>
#include <cuda_fp16.h>
#include <math.h>
#include <float.h>
#include <stdint.h>

#define N 8192
#define D 128
#define BM 128
#define BN 128
#define NBLK 64                         // 64 row/col blocks of 128
#define TOT_TILES (NBLK * (NBLK + 1) / 2)   // 2080
#define NCTA 296                        // 2 CTAs per SM
#define TBASE (TOT_TILES / NCTA)        // 7
#define TREM  (TOT_TILES - TBASE * NCTA)  // 8
#define MARGIN 0.05f
#define TS 272                          // smem row stride bytes
#define NTHREADS 256

// ---------------- device scratch ----------------
__device__ __half g_hi[N * D];
__device__ float g_sq[N];
__device__ unsigned g_dminP[N];   // ordered-uint: min dot over positives
__device__ unsigned g_dmaxN[N];   // ordered-uint: max dot over negatives
__device__ int g_done;            // CTA completion counter (reset each call)

// ---------------- smem layout (bytes) ----------------
#define T_BYTES (128 * TS)                    // 34816
#define SM_A       0
#define SM_B(b)    (T_BYTES + (b) * T_BYTES)
#define SM_LAB(b)  (3 * T_BYTES + (b) * 512)
#define SM_RED     (3 * T_BYTES + 1024)       // [4][128] min + [4][128] max
#define SM_FLAG    (SM_RED + 4096)
#define SM_TOTAL   (SM_FLAG + 16)             // ~109.6KB -> 2 CTAs/SM

__device__ __forceinline__ uint32_t smem_u32(const void* p) {
    uint32_t a;
    asm("{ .reg .u64 t; cvta.to.shared.u64 t, %1; cvt.u32.u64 %0, t; }" : "=r"(a) : "l"(p));
    return a;
}
#define CP16(dst, src) \
    asm volatile("cp.async.cg.shared.global [%0], [%1], 16;" :: "r"(dst), "l"(src) : "memory")
#define CP_COMMIT() asm volatile("cp.async.commit_group;" ::: "memory")
#define CP_WAIT0()  asm volatile("cp.async.wait_group 0;" ::: "memory")

__device__ __forceinline__ void ldm_x4(uint32_t* r, uint32_t addr) {
    asm volatile("ldmatrix.sync.aligned.m8n8.x4.shared.b16 {%0,%1,%2,%3}, [%4];"
                 : "=r"(r[0]), "=r"(r[1]), "=r"(r[2]), "=r"(r[3]) : "r"(addr));
}
__device__ __forceinline__ void mma_f32(float* c, const uint32_t* a, const uint32_t* b) {
    asm volatile(
        "mma.sync.aligned.m16n8k16.row.col.f32.f16.f16.f32 "
        "{%0,%1,%2,%3}, {%4,%5,%6,%7}, {%8,%9}, {%0,%1,%2,%3};"
        : "+f"(c[0]), "+f"(c[1]), "+f"(c[2]), "+f"(c[3])
        : "r"(a[0]), "r"(a[1]), "r"(a[2]), "r"(a[3]), "r"(b[0]), "r"(b[1]));
}

__device__ __forceinline__ unsigned f2ord(float f) {
    unsigned b = __float_as_uint(f);
    return (b & 0x80000000u) ? ~b : (b | 0x80000000u);
}
__device__ __forceinline__ float ord2f(unsigned u) {
    unsigned b = (u & 0x80000000u) ? (u ^ 0x80000000u) : ~u;
    return __uint_as_float(b);
}
// tiles before row block rt (coverage: ct >= rt)
__device__ __forceinline__ int cumt(int rt) {
    return rt * NBLK - (rt * (rt - 1)) / 2;
}

// ---------------------------------------------------------------------------
// Kernel 1: normalize rows -> fp16 + fp32 sumsq; init atomics + counter.
__global__ void normalize_kernel(const float* __restrict__ x) {
    int tid    = threadIdx.x;
    int row    = blockIdx.x * 16 + (tid >> 4);
    int lane16 = tid & 15;
    if (blockIdx.x == 0 && tid == 0) g_done = 0;
    const float4* xr = (const float4*)(x + (size_t)row * D);
    float4 v[2];
    float s = 0.0f;
#pragma unroll
    for (int j = 0; j < 2; j++) {
        v[j] = xr[lane16 + 16 * j];
        s += v[j].x * v[j].x + v[j].y * v[j].y + v[j].z * v[j].z + v[j].w * v[j].w;
    }
#pragma unroll
    for (int o = 8; o; o >>= 1) s += __shfl_xor_sync(0xffffffffu, s, o);
    float r = 1.0f / fmaxf(sqrtf(s), 1e-12f);
    float s2 = 0.0f;
    uint2* hr = (uint2*)(g_hi + (size_t)row * D);
#pragma unroll
    for (int j = 0; j < 2; j++) {
        float o0 = v[j].x * r, o1 = v[j].y * r, o2 = v[j].z * r, o3 = v[j].w * r;
        s2 += o0 * o0 + o1 * o1 + o2 * o2 + o3 * o3;
        uint32_t p0 = (uint32_t)__half_as_ushort(__float2half_rn(o0)) |
                      ((uint32_t)__half_as_ushort(__float2half_rn(o1)) << 16);
        uint32_t p1 = (uint32_t)__half_as_ushort(__float2half_rn(o2)) |
                      ((uint32_t)__half_as_ushort(__float2half_rn(o3)) << 16);
        hr[lane16 + 16 * j] = make_uint2(p0, p1);
    }
#pragma unroll
    for (int o = 8; o; o >>= 1) s2 += __shfl_xor_sync(0xffffffffu, s2, o);
    if (lane16 == 0) {
        g_sq[row] = s2;
        g_dminP[row] = f2ord(FLT_MAX);
        g_dmaxN[row] = f2ord(-FLT_MAX);
    }
}

// ---------------------------------------------------------------------------
// Kernel 2: persistent fused 1-term fp16 GEMM + batch-hard mining + finalize.
// 296 CTAs (2/SM). CTA tile 128x128; 8 warps (2m x 4n), warp tile 64x32.
// Upper triangle; off-diag tiles column-flush via direct REDG (all lanes,
// no shfl tree). Last CTA to finish runs the finalize reduction.
__global__ __launch_bounds__(NTHREADS, 2)
void tile_kernel(const int* __restrict__ labels, float* __restrict__ out) {
    extern __shared__ char smem[];
    const uint32_t sb = smem_u32(smem);
    const int tid  = threadIdx.x;
    const int lane = tid & 31;
    const int wid  = tid >> 5;
    const int wm   = wid & 1;      // 2 warp rows (64 each)
    const int wn   = wid >> 1;     // 4 warp cols (32 each)
    const int bid  = blockIdx.x;

    const int start = bid * TBASE + min(bid, TREM);
    const int tend  = start + TBASE + (bid < TREM ? 1 : 0);

    const uint32_t aLane = (uint32_t)((wm * 64 + (lane & 7) + ((lane >> 3) & 1) * 8) * TS
                                      + (lane >> 4) * 16);
    // B paired ldmatrix.x4: m0=(ntE,k0) m1=(ntE,k1) m2=(ntO,k0) m3=(ntO,k1)
    const uint32_t bLane = (uint32_t)((wn * 32 + ((lane >> 4) * 8) + (lane & 7)) * TS
                                      + (((lane >> 3) & 1) * 16));

    auto loadA = [&](int rowBase) {
        const char* sH = (const char*)g_hi + (size_t)rowBase * D * 2;
#pragma unroll
        for (int i = 0; i < 8; i++) {
            int q = tid + i * NTHREADS;
            int r = q >> 4, kc = q & 15;
            CP16(sb + SM_A + r * TS + kc * 16, sH + (size_t)r * 256 + kc * 16);
        }
    };
    auto loadB = [&](int ct, int b) {
        int colBase = ct * BN;
        const char* sH = (const char*)g_hi + (size_t)colBase * D * 2;
#pragma unroll
        for (int i = 0; i < 8; i++) {
            int q = tid + i * NTHREADS;
            int r = q >> 4, kc = q & 15;
            CP16(sb + SM_B(b) + r * TS + kc * 16, sH + (size_t)r * 256 + kc * 16);
        }
        if (tid < BN)
            *(int*)(smem + SM_LAB(b) + tid * 4) = labels[colBase + tid];
        CP_COMMIT();
    };

    int t = start;
    int rt = 0;
    while (cumt(rt + 1) <= t) rt++;

    while (t < tend) {
        const int rowBase = rt * BM;
        const int segEnd = min(tend, cumt(rt + 1));
        const int ct0 = rt + (t - cumt(rt));

        loadA(rowBase);
        loadB(ct0, 0);
        CP_WAIT0();
        __syncthreads();

        int rowlab[4][2];
#pragma unroll
        for (int mt = 0; mt < 4; mt++)
#pragma unroll
            for (int h = 0; h < 2; h++)
                rowlab[mt][h] = labels[rowBase + wm * 64 + mt * 16 + h * 8 + (lane >> 2)];

        float rminP[4][2], rmaxN[4][2];
#pragma unroll
        for (int mt = 0; mt < 4; mt++)
#pragma unroll
            for (int h = 0; h < 2; h++) { rminP[mt][h] = FLT_MAX; rmaxN[mt][h] = -FLT_MAX; }

        for (int tt = t; tt < segEnd; tt++) {
            const int ct = rt + (tt - cumt(rt));
            const int b  = (tt - t) & 1;
            const bool offDiag = (ct != rt);
            if (tt + 1 < segEnd) loadB(ct + 1, b ^ 1);

            float acc[4][4][4];
#pragma unroll
            for (int mt = 0; mt < 4; mt++)
#pragma unroll
                for (int nt = 0; nt < 4; nt++)
#pragma unroll
                    for (int i = 0; i < 4; i++) acc[mt][nt][i] = 0.0f;

            const uint32_t AA = sb + SM_A, BB = sb + SM_B(b);
#pragma unroll
            for (int ks = 0; ks < 8; ks++) {
                uint32_t bH[2][4];    // bH[p] = {nt2p:k0,k1, nt2p+1:k0,k1}
#pragma unroll
                for (int p = 0; p < 2; p++)
                    ldm_x4(bH[p], BB + bLane + (uint32_t)(p * 16 * TS + ks * 32));
#pragma unroll
                for (int mt = 0; mt < 4; mt++) {
                    uint32_t aH[4];
                    ldm_x4(aH, AA + aLane + (uint32_t)(mt * 16 * TS + ks * 32));
#pragma unroll
                    for (int nt = 0; nt < 4; nt++)
                        mma_f32(acc[mt][nt], aH, &bH[nt >> 1][(nt & 1) * 2]);
                }
            }

            // epilogue: mine dot extrema; column partials flushed via direct
            // REDG from every lane (8 lanes share a column; L2 reduces).
            const int* labS = (const int*)(smem + SM_LAB(b));
            const int colBase = ct * BN;
#pragma unroll
            for (int nt = 0; nt < 4; nt++) {
                int nl0 = wn * 32 + nt * 8 + 2 * (lane & 3);
                int lb0 = labS[nl0], lb1 = labS[nl0 + 1];
                float c0n = FLT_MAX, c0x = -FLT_MAX, c1n = FLT_MAX, c1x = -FLT_MAX;
#pragma unroll
                for (int mt = 0; mt < 4; mt++)
#pragma unroll
                    for (int h = 0; h < 2; h++) {
                        float d0 = acc[mt][nt][2 * h];
                        float d1 = acc[mt][nt][2 * h + 1];
                        int rl = rowlab[mt][h];
                        if (rl == lb0) {
                            rminP[mt][h] = fminf(rminP[mt][h], d0);
                            c0n = fminf(c0n, d0);
                        } else {
                            rmaxN[mt][h] = fmaxf(rmaxN[mt][h], d0);
                            c0x = fmaxf(c0x, d0);
                        }
                        if (rl == lb1) {
                            rminP[mt][h] = fminf(rminP[mt][h], d1);
                            c1n = fminf(c1n, d1);
                        } else {
                            rmaxN[mt][h] = fmaxf(rmaxN[mt][h], d1);
                            c1x = fmaxf(c1x, d1);
                        }
                    }
                if (offDiag) {
                    int cg = colBase + nl0;
                    atomicMin(&g_dminP[cg], f2ord(c0n));      // REDG.MIN
                    atomicMax(&g_dmaxN[cg], f2ord(c0x));
                    atomicMin(&g_dminP[cg + 1], f2ord(c1n));
                    atomicMax(&g_dmaxN[cg + 1], f2ord(c1x));
                }
            }

            if (tt + 1 < segEnd) CP_WAIT0();
            __syncthreads();
        }

        // row-anchor flush for this rt segment
#pragma unroll
        for (int mt = 0; mt < 4; mt++)
#pragma unroll
            for (int h = 0; h < 2; h++)
#pragma unroll
                for (int off = 1; off <= 2; off <<= 1) {
                    rminP[mt][h] = fminf(rminP[mt][h], __shfl_xor_sync(0xffffffffu, rminP[mt][h], off));
                    rmaxN[mt][h] = fmaxf(rmaxN[mt][h], __shfl_xor_sync(0xffffffffu, rmaxN[mt][h], off));
                }
        float* redmin = (float*)(smem + SM_RED);   // [4 wn][128]
        float* redmax = redmin + 4 * 128;
        if ((lane & 3) == 0) {
#pragma unroll
            for (int mt = 0; mt < 4; mt++)
#pragma unroll
                for (int h = 0; h < 2; h++) {
                    int rl = wm * 64 + mt * 16 + h * 8 + (lane >> 2);
                    redmin[wn * 128 + rl] = rminP[mt][h];
                    redmax[wn * 128 + rl] = rmaxN[mt][h];
                }
        }
        __syncthreads();
        if (tid < BM) {
            float mn = FLT_MAX, mx = -FLT_MAX;
#pragma unroll
            for (int w = 0; w < 4; w++) {
                mn = fminf(mn, redmin[w * 128 + tid]);
                mx = fmaxf(mx, redmax[w * 128 + tid]);
            }
            atomicMin(&g_dminP[rowBase + tid], f2ord(mn));
            atomicMax(&g_dmaxN[rowBase + tid], f2ord(mx));
        }
        __syncthreads();
        t = segEnd;
        rt++;
    }

    // ---------------- fused finalize: last CTA reduces ----------------
    __threadfence();
    int* s_last = (int*)(smem + SM_FLAG);
    if (tid == 0) *s_last = (atomicAdd(&g_done, 1) == NCTA - 1) ? 1 : 0;
    __syncthreads();
    if (*s_last) {
        __shared__ float ssum[NTHREADS];
        __shared__ int   scnt[NTHREADS];
        float sum = 0.0f;
        int   cnt = 0;
        for (int i = tid; i < N; i += NTHREADS) {
            float mp = ord2f(g_dminP[i]);
            float mn = ord2f(g_dmaxN[i]);
            float sqi = g_sq[i];
            float dap = sqrtf(fmaxf(sqi + 1.0f - 2.0f * mp, 0.0f));
            float dan = sqrtf(fmaxf(sqi + 1.0f - 2.0f * mn, 0.0f));
            float per = fmaxf(dap - dan + MARGIN, 0.0f);
            if (per > 0.0f) { sum += per; cnt++; }
        }
        ssum[tid] = sum; scnt[tid] = cnt;
        __syncthreads();
        for (int o = NTHREADS / 2; o; o >>= 1) {
            if (tid < o) { ssum[tid] += ssum[tid + o]; scnt[tid] += scnt[tid + o]; }
            __syncthreads();
        }
        if (tid == 0) out[0] = (scnt[0] > 0) ? (ssum[0] / (float)scnt[0]) : 0.0f;
    }
}

// ---------------------------------------------------------------------------
extern "C" void kernel_launch(void* const* d_in, const int* in_sizes, int n_in,
                              void* d_out, int out_size) {
    const float* x      = (const float*)d_in[0];
    const int*   labels = (const int*)d_in[1];

    normalize_kernel<<<N / 16, 256>>>(x);

    cudaFuncSetAttribute(tile_kernel,
                         cudaFuncAttributeMaxDynamicSharedMemorySize, SM_TOTAL);
    tile_kernel<<<NCTA, NTHREADS, SM_TOTAL>>>(labels, (float*)d_out);
}

// round 16
// speedup vs baseline: 1.6960x; 1.6960x over previous
#include <cuda_runtime.h>
#include <cuda_fp16.h>
#include <math.h>
#include <float.h>
#include <stdint.h>

#define N 8192
#define D 128
#define BM 128
#define BN 128
#define NBLK 64                         // 64 row/col blocks of 128
#define TOT_TILES (NBLK * (NBLK + 1) / 2)   // 2080
#define NCTA 296                        // 2 CTAs per SM
#define TBASE (TOT_TILES / NCTA)        // 7
#define TREM  (TOT_TILES - TBASE * NCTA)  // 8
#define MARGIN 0.05f
#define TS 272                          // smem row stride bytes
#define NTHREADS 256

// ---------------- device scratch ----------------
__device__ __half g_hi[N * D];
__device__ float g_sq[N];
__device__ unsigned g_dminP[N];   // ordered-uint: min dot over positives
__device__ unsigned g_dmaxN[N];   // ordered-uint: max dot over negatives

// ---------------- smem layout (bytes) ----------------
#define T_BYTES (128 * TS)                    // 34816
#define SM_A       0
#define SM_B(b)    (T_BYTES + (b) * T_BYTES)
#define SM_LAB(b)  (3 * T_BYTES + (b) * 512)
#define SM_RED     (3 * T_BYTES + 1024)       // [4][128] min + [4][128] max
#define SM_TOTAL   (SM_RED + 4096)            // 109568 -> 2 CTAs/SM

__device__ __forceinline__ uint32_t smem_u32(const void* p) {
    uint32_t a;
    asm("{ .reg .u64 t; cvta.to.shared.u64 t, %1; cvt.u32.u64 %0, t; }" : "=r"(a) : "l"(p));
    return a;
}
#define CP16(dst, src) \
    asm volatile("cp.async.cg.shared.global [%0], [%1], 16;" :: "r"(dst), "l"(src) : "memory")
#define CP_COMMIT() asm volatile("cp.async.commit_group;" ::: "memory")
#define CP_WAIT0()  asm volatile("cp.async.wait_group 0;" ::: "memory")

__device__ __forceinline__ void ldm_x4(uint32_t* r, uint32_t addr) {
    asm volatile("ldmatrix.sync.aligned.m8n8.x4.shared.b16 {%0,%1,%2,%3}, [%4];"
                 : "=r"(r[0]), "=r"(r[1]), "=r"(r[2]), "=r"(r[3]) : "r"(addr));
}
__device__ __forceinline__ void mma_f32(float* c, const uint32_t* a, const uint32_t* b) {
    asm volatile(
        "mma.sync.aligned.m16n8k16.row.col.f32.f16.f16.f32 "
        "{%0,%1,%2,%3}, {%4,%5,%6,%7}, {%8,%9}, {%0,%1,%2,%3};"
        : "+f"(c[0]), "+f"(c[1]), "+f"(c[2]), "+f"(c[3])
        : "r"(a[0]), "r"(a[1]), "r"(a[2]), "r"(a[3]), "r"(b[0]), "r"(b[1]));
}

__device__ __forceinline__ unsigned f2ord(float f) {
    unsigned b = __float_as_uint(f);
    return (b & 0x80000000u) ? ~b : (b | 0x80000000u);
}
__device__ __forceinline__ float ord2f(unsigned u) {
    unsigned b = (u & 0x80000000u) ? (u ^ 0x80000000u) : ~u;
    return __uint_as_float(b);
}
// tiles before row block rt (coverage: ct >= rt)
__device__ __forceinline__ int cumt(int rt) {
    return rt * NBLK - (rt * (rt - 1)) / 2;
}

// ---------------------------------------------------------------------------
// Kernel 1: normalize rows -> fp16 + fp32 sumsq; init atomic arrays.
__global__ void normalize_kernel(const float* __restrict__ x) {
    int tid    = threadIdx.x;
    int row    = blockIdx.x * 16 + (tid >> 4);
    int lane16 = tid & 15;
    const float4* xr = (const float4*)(x + (size_t)row * D);
    float4 v[2];
    float s = 0.0f;
#pragma unroll
    for (int j = 0; j < 2; j++) {
        v[j] = xr[lane16 + 16 * j];
        s += v[j].x * v[j].x + v[j].y * v[j].y + v[j].z * v[j].z + v[j].w * v[j].w;
    }
#pragma unroll
    for (int o = 8; o; o >>= 1) s += __shfl_xor_sync(0xffffffffu, s, o);
    float r = 1.0f / fmaxf(sqrtf(s), 1e-12f);
    float s2 = 0.0f;
    uint2* hr = (uint2*)(g_hi + (size_t)row * D);
#pragma unroll
    for (int j = 0; j < 2; j++) {
        float o0 = v[j].x * r, o1 = v[j].y * r, o2 = v[j].z * r, o3 = v[j].w * r;
        s2 += o0 * o0 + o1 * o1 + o2 * o2 + o3 * o3;
        uint32_t p0 = (uint32_t)__half_as_ushort(__float2half_rn(o0)) |
                      ((uint32_t)__half_as_ushort(__float2half_rn(o1)) << 16);
        uint32_t p1 = (uint32_t)__half_as_ushort(__float2half_rn(o2)) |
                      ((uint32_t)__half_as_ushort(__float2half_rn(o3)) << 16);
        hr[lane16 + 16 * j] = make_uint2(p0, p1);
    }
#pragma unroll
    for (int o = 8; o; o >>= 1) s2 += __shfl_xor_sync(0xffffffffu, s2, o);
    if (lane16 == 0) {
        g_sq[row] = s2;
        g_dminP[row] = f2ord(FLT_MAX);
        g_dmaxN[row] = f2ord(-FLT_MAX);
    }
}

// ---------------------------------------------------------------------------
// Kernel 2: persistent fused 1-term fp16 GEMM + batch-hard mining.
// 296 CTAs (2/SM). CTA tile 128x128; 8 warps (2m x 4n), warp tile 64x32.
// Upper triangle; off-diag tiles mined both ways; diagonal tiles skip the
// (redundant) column flush. Column flush: 2-level shfl + lane<8 atomics.
__global__ __launch_bounds__(NTHREADS, 2)
void tile_kernel(const int* __restrict__ labels) {
    extern __shared__ char smem[];
    const uint32_t sb = smem_u32(smem);
    const int tid  = threadIdx.x;
    const int lane = tid & 31;
    const int wid  = tid >> 5;
    const int wm   = wid & 1;      // 2 warp rows (64 each)
    const int wn   = wid >> 1;     // 4 warp cols (32 each)
    const int bid  = blockIdx.x;

    const int start = bid * TBASE + min(bid, TREM);
    const int tend  = start + TBASE + (bid < TREM ? 1 : 0);

    const uint32_t aLane = (uint32_t)((wm * 64 + (lane & 7) + ((lane >> 3) & 1) * 8) * TS
                                      + (lane >> 4) * 16);
    // B paired ldmatrix.x4: m0=(ntE,k0) m1=(ntE,k1) m2=(ntO,k0) m3=(ntO,k1)
    const uint32_t bLane = (uint32_t)((wn * 32 + ((lane >> 4) * 8) + (lane & 7)) * TS
                                      + (((lane >> 3) & 1) * 16));

    auto loadA = [&](int rowBase) {
        const char* sH = (const char*)g_hi + (size_t)rowBase * D * 2;
#pragma unroll
        for (int i = 0; i < 8; i++) {
            int q = tid + i * NTHREADS;
            int r = q >> 4, kc = q & 15;
            CP16(sb + SM_A + r * TS + kc * 16, sH + (size_t)r * 256 + kc * 16);
        }
    };
    auto loadB = [&](int ct, int b) {
        int colBase = ct * BN;
        const char* sH = (const char*)g_hi + (size_t)colBase * D * 2;
#pragma unroll
        for (int i = 0; i < 8; i++) {
            int q = tid + i * NTHREADS;
            int r = q >> 4, kc = q & 15;
            CP16(sb + SM_B(b) + r * TS + kc * 16, sH + (size_t)r * 256 + kc * 16);
        }
        if (tid < BN)
            *(int*)(smem + SM_LAB(b) + tid * 4) = labels[colBase + tid];
        CP_COMMIT();
    };

    int t = start;
    int rt = 0;
    while (cumt(rt + 1) <= t) rt++;

    while (t < tend) {
        const int rowBase = rt * BM;
        const int segEnd = min(tend, cumt(rt + 1));
        const int ct0 = rt + (t - cumt(rt));

        loadA(rowBase);
        loadB(ct0, 0);
        CP_WAIT0();
        __syncthreads();

        int rowlab[4][2];
#pragma unroll
        for (int mt = 0; mt < 4; mt++)
#pragma unroll
            for (int h = 0; h < 2; h++)
                rowlab[mt][h] = labels[rowBase + wm * 64 + mt * 16 + h * 8 + (lane >> 2)];

        float rminP[4][2], rmaxN[4][2];
#pragma unroll
        for (int mt = 0; mt < 4; mt++)
#pragma unroll
            for (int h = 0; h < 2; h++) { rminP[mt][h] = FLT_MAX; rmaxN[mt][h] = -FLT_MAX; }

        for (int tt = t; tt < segEnd; tt++) {
            const int ct = rt + (tt - cumt(rt));
            const int b  = (tt - t) & 1;
            const bool offDiag = (ct != rt);
            if (tt + 1 < segEnd) loadB(ct + 1, b ^ 1);

            float acc[4][4][4];
#pragma unroll
            for (int mt = 0; mt < 4; mt++)
#pragma unroll
                for (int nt = 0; nt < 4; nt++)
#pragma unroll
                    for (int i = 0; i < 4; i++) acc[mt][nt][i] = 0.0f;

            const uint32_t AA = sb + SM_A, BB = sb + SM_B(b);
#pragma unroll
            for (int ks = 0; ks < 8; ks++) {
                uint32_t bH[2][4];    // bH[p] = {nt2p:k0,k1, nt2p+1:k0,k1}
#pragma unroll
                for (int p = 0; p < 2; p++)
                    ldm_x4(bH[p], BB + bLane + (uint32_t)(p * 16 * TS + ks * 32));
#pragma unroll
                for (int mt = 0; mt < 4; mt++) {
                    uint32_t aH[4];
                    ldm_x4(aH, AA + aLane + (uint32_t)(mt * 16 * TS + ks * 32));
#pragma unroll
                    for (int nt = 0; nt < 4; nt++)
                        mma_f32(acc[mt][nt], aH, &bH[nt >> 1][(nt & 1) * 2]);
                }
            }

            // epilogue: mine dot extrema; column flush: 2-level shfl (off=8,16)
            // leaves 2 partials per column in lanes<8; both flushed via atomics.
            const int* labS = (const int*)(smem + SM_LAB(b));
            const int colBase = ct * BN;
#pragma unroll
            for (int nt = 0; nt < 4; nt++) {
                int nl0 = wn * 32 + nt * 8 + 2 * (lane & 3);
                int lb0 = labS[nl0], lb1 = labS[nl0 + 1];
                float c0n = FLT_MAX, c0x = -FLT_MAX, c1n = FLT_MAX, c1x = -FLT_MAX;
#pragma unroll
                for (int mt = 0; mt < 4; mt++)
#pragma unroll
                    for (int h = 0; h < 2; h++) {
                        float d0 = acc[mt][nt][2 * h];
                        float d1 = acc[mt][nt][2 * h + 1];
                        int rl = rowlab[mt][h];
                        if (rl == lb0) {
                            rminP[mt][h] = fminf(rminP[mt][h], d0);
                            c0n = fminf(c0n, d0);
                        } else {
                            rmaxN[mt][h] = fmaxf(rmaxN[mt][h], d0);
                            c0x = fmaxf(c0x, d0);
                        }
                        if (rl == lb1) {
                            rminP[mt][h] = fminf(rminP[mt][h], d1);
                            c1n = fminf(c1n, d1);
                        } else {
                            rmaxN[mt][h] = fmaxf(rmaxN[mt][h], d1);
                            c1x = fmaxf(c1x, d1);
                        }
                    }
                if (offDiag) {
#pragma unroll
                    for (int off = 8; off <= 16; off <<= 1) {
                        c0n = fminf(c0n, __shfl_xor_sync(0xffffffffu, c0n, off));
                        c0x = fmaxf(c0x, __shfl_xor_sync(0xffffffffu, c0x, off));
                        c1n = fminf(c1n, __shfl_xor_sync(0xffffffffu, c1n, off));
                        c1x = fmaxf(c1x, __shfl_xor_sync(0xffffffffu, c1x, off));
                    }
                    if (lane < 8) {      // lanes 0-3 and 4-7: two partials/col
                        int cg = colBase + wn * 32 + nt * 8 + 2 * (lane & 3);
                        atomicMin(&g_dminP[cg], f2ord(c0n));
                        atomicMax(&g_dmaxN[cg], f2ord(c0x));
                        atomicMin(&g_dminP[cg + 1], f2ord(c1n));
                        atomicMax(&g_dmaxN[cg + 1], f2ord(c1x));
                    }
                }
            }

            if (tt + 1 < segEnd) CP_WAIT0();
            __syncthreads();
        }

        // row-anchor flush for this rt segment
#pragma unroll
        for (int mt = 0; mt < 4; mt++)
#pragma unroll
            for (int h = 0; h < 2; h++)
#pragma unroll
                for (int off = 1; off <= 2; off <<= 1) {
                    rminP[mt][h] = fminf(rminP[mt][h], __shfl_xor_sync(0xffffffffu, rminP[mt][h], off));
                    rmaxN[mt][h] = fmaxf(rmaxN[mt][h], __shfl_xor_sync(0xffffffffu, rmaxN[mt][h], off));
                }
        float* redmin = (float*)(smem + SM_RED);   // [4 wn][128]
        float* redmax = redmin + 4 * 128;
        if ((lane & 3) == 0) {
#pragma unroll
            for (int mt = 0; mt < 4; mt++)
#pragma unroll
                for (int h = 0; h < 2; h++) {
                    int rl = wm * 64 + mt * 16 + h * 8 + (lane >> 2);
                    redmin[wn * 128 + rl] = rminP[mt][h];
                    redmax[wn * 128 + rl] = rmaxN[mt][h];
                }
        }
        __syncthreads();
        if (tid < BM) {
            float mn = FLT_MAX, mx = -FLT_MAX;
#pragma unroll
            for (int w = 0; w < 4; w++) {
                mn = fminf(mn, redmin[w * 128 + tid]);
                mx = fmaxf(mx, redmax[w * 128 + tid]);
            }
            atomicMin(&g_dminP[rowBase + tid], f2ord(mn));
            atomicMax(&g_dmaxN[rowBase + tid], f2ord(mx));
        }
        __syncthreads();
        t = segEnd;
        rt++;
    }
}

// ---------------------------------------------------------------------------
// Kernel 3: per-anchor loss + AvgNonZero reduction.
// d^2 = sq_i + 1 - 2*dot  (sq_j ~ 1 within 1e-7 for normalized rows)
__global__ void finalize_kernel(float* __restrict__ out) {
    __shared__ float ssum[1024];
    __shared__ int   scnt[1024];
    int t = threadIdx.x;
    float sum = 0.0f;
    int   cnt = 0;
    for (int i = t; i < N; i += 1024) {
        float mp = ord2f(g_dminP[i]);
        float mn = ord2f(g_dmaxN[i]);
        float sqi = g_sq[i];
        float dap = sqrtf(fmaxf(sqi + 1.0f - 2.0f * mp, 0.0f));
        float dan = sqrtf(fmaxf(sqi + 1.0f - 2.0f * mn, 0.0f));
        float per = fmaxf(dap - dan + MARGIN, 0.0f);
        if (per > 0.0f) { sum += per; cnt++; }
    }
    ssum[t] = sum; scnt[t] = cnt;
    __syncthreads();
    for (int o = 512; o; o >>= 1) {
        if (t < o) { ssum[t] += ssum[t + o]; scnt[t] += scnt[t + o]; }
        __syncthreads();
    }
    if (t == 0) out[0] = (scnt[0] > 0) ? (ssum[0] / (float)scnt[0]) : 0.0f;
}

// ---------------------------------------------------------------------------
extern "C" void kernel_launch(void* const* d_in, const int* in_sizes, int n_in,
                              void* d_out, int out_size) {
    const float* x      = (const float*)d_in[0];
    const int*   labels = (const int*)d_in[1];

    normalize_kernel<<<N / 16, 256>>>(x);

    cudaFuncSetAttribute(tile_kernel,
                         cudaFuncAttributeMaxDynamicSharedMemorySize, SM_TOTAL);
    tile_kernel<<<NCTA, NTHREADS, SM_TOTAL>>>(labels);

    finalize_kernel<<<1, 1024>>>((float*)d_out);
}